// round 4
// baseline (speedup 1.0000x reference)
#include <cuda_runtime.h>
#include <cstdint>

// Problem constants (fixed by the dataset)
#define IN_F    512
#define GATES   255
#define GATES_P 256
#define LEAVES  256
#define OUT_F   256
#define BM      64     // rows per block
#define KC      32     // K-chunk for gate GEMM
#define LC      32     // L-chunk for leaf GEMM
#define NTHREADS 256

// Scratch: z transposed to [leaf][out] for coalesced phase-3 tile loads.
__device__ float g_zT[LEAVES * OUT_F];

typedef unsigned long long u64;

__device__ __forceinline__ u64 pack_dup(float a) {
    u64 r; asm("mov.b64 %0, {%1, %1};" : "=l"(r) : "f"(a)); return r;
}
__device__ __forceinline__ u64 pack2(float lo, float hi) {
    u64 r; asm("mov.b64 %0, {%1, %2};" : "=l"(r) : "f"(lo), "f"(hi)); return r;
}
__device__ __forceinline__ u64 fma2(u64 a, u64 b, u64 c) {
    u64 d; asm("fma.rn.f32x2 %0, %1, %2, %3;" : "=l"(d) : "l"(a), "l"(b), "l"(c)); return d;
}
__device__ __forceinline__ float2 unpk(u64 v) {
    float2 f; asm("mov.b64 {%0, %1}, %2;" : "=f"(f.x), "=f"(f.y) : "l"(v)); return f;
}

__global__ void transpose_z_kernel(const float* __restrict__ z) {
    int idx = blockIdx.x * blockDim.x + threadIdx.x;   // 65536 threads
    int o = idx >> 8;
    int l = idx & 255;
    g_zT[l * OUT_F + o] = z[o * LEAVES + l];
}

// Dynamic smem layout (floats):
//   [0, 2048)          xs  [64][32]        (phase 1)         -- overlaps gl
//   [2048, 10240)      ws  [32][256]       (phase 1)         -- overlaps gl
//   [0, 16384)         gl  [64][256]       gates, then leaf  (phases 2,3)
//   [16384, 24576)     zs  [32][256]       (phase 3)
//   [24576, 24832)     gbs [256]
// total: 24832 floats = 99328 bytes
#define SMEM_FLOATS 24832

extern "C" __global__ void __launch_bounds__(NTHREADS, 2)
softtree_fused_kernel(const float* __restrict__ x,
                      const float* __restrict__ gw,
                      const float* __restrict__ gb,
                      float* __restrict__ out)
{
    extern __shared__ float smem[];
    float* xs  = smem;                  // [64][32]
    float* ws  = smem + BM * KC;        // [32][256]
    float* gl  = smem;                  // [64][256] gates then leaf
    float* zs  = smem + 16384;          // [32][256]
    float* gbs = smem + 16384 + 8192;   // [256]

    const int tid = threadIdx.x;
    const int tx  = tid & 31;           // 32 col-groups of 8 cols
    const int ty  = tid >> 5;           // 8 row-groups of 8 rows
    const int rbase = blockIdx.x * BM;

    gbs[tid] = (tid < GATES) ? gb[tid] : 0.0f;

    // 8x8 fp32 microtile, packed as 8 x 4 f32x2 accumulators
    u64 acc[8][4];
    #pragma unroll
    for (int i = 0; i < 8; i++)
        #pragma unroll
        for (int j = 0; j < 4; j++) acc[i][j] = 0ull;

    // ---------------- Phase 1: gate logits = x @ gw ----------------
    for (int kt = 0; kt < IN_F / KC; kt++) {
        __syncthreads();
        // load x tile [64][32] (2 float4 per thread, coalesced)
        #pragma unroll
        for (int t = 0; t < 2; t++) {
            int f  = tid + t * NTHREADS;     // float4 slot 0..511
            int r  = f >> 3;
            int kq = f & 7;
            float4 v = *(const float4*)&x[(size_t)(rbase + r) * IN_F + kt * KC + kq * 4];
            *(float4*)&xs[r * KC + kq * 4] = v;
        }
        // load gw tile [32][256] (gw is [512][255] row-major; pad col 255 with 0)
        #pragma unroll 8
        for (int t = 0; t < 32; t++) {
            int idx = tid + t * NTHREADS;
            int k = idx >> 8;
            int g = idx & 255;
            ws[k * GATES_P + g] = (g < GATES) ? gw[(size_t)(kt * KC + k) * GATES + g] : 0.0f;
        }
        __syncthreads();
        #pragma unroll 8
        for (int kk = 0; kk < KC; kk++) {
            const ulonglong2* bp = (const ulonglong2*)&ws[kk * GATES_P + tx * 8];
            ulonglong2 b01 = bp[0];
            ulonglong2 b23 = bp[1];
            u64 b0 = b01.x, b1 = b01.y, b2 = b23.x, b3 = b23.y;
            #pragma unroll
            for (int i = 0; i < 8; i++) {
                u64 a2 = pack_dup(xs[(ty * 8 + i) * KC + kk]);
                acc[i][0] = fma2(a2, b0, acc[i][0]);
                acc[i][1] = fma2(a2, b1, acc[i][1]);
                acc[i][2] = fma2(a2, b2, acc[i][2]);
                acc[i][3] = fma2(a2, b3, acc[i][3]);
            }
        }
    }
    __syncthreads();   // everyone done reading xs/ws before gl overwrites them

    // ---------------- Phase 2a: sigmoid -> gates in smem ----------------
    #pragma unroll
    for (int i = 0; i < 8; i++) {
        int r = ty * 8 + i;
        #pragma unroll
        for (int j = 0; j < 4; j++) {
            float2 v = unpk(acc[i][j]);
            int c = tx * 8 + j * 2;
            float l0 = v.x + gbs[c];
            float l1 = v.y + gbs[c + 1];
            gl[r * GATES_P + c]     = 1.0f / (1.0f + __expf(-l0));
            gl[r * GATES_P + c + 1] = 1.0f / (1.0f + __expf(-l1));
        }
    }
    __syncthreads();

    // ---------------- Phase 2b: tree products -> leaf probs ----------------
    // leaf l (0..255): depth d uses node (2^d - 1) + (l >> (8-d)),
    // factor = bit ? (1-g) : g with bit = (l >> (7-d)) & 1.
    // Depths 0..4 depend only on tx (shared across the thread's 8 leaves).
    #pragma unroll
    for (int i = 0; i < 8; i++) {
        const float* grow = &gl[(ty * 8 + i) * GATES_P];
        float common = 1.0f;
        #pragma unroll
        for (int d = 0; d < 5; d++) {
            int prefix = tx >> (5 - d);
            float g = grow[(1 << d) - 1 + prefix];
            int bit = (tx >> (4 - d)) & 1;
            common *= bit ? (1.0f - g) : g;
        }
        #pragma unroll
        for (int jp = 0; jp < 4; jp++) {
            float pv[2];
            #pragma unroll
            for (int s = 0; s < 2; s++) {
                int l = tx * 8 + jp * 2 + s;
                float p = common;
                #pragma unroll
                for (int d = 5; d < 8; d++) {
                    int prefix = l >> (8 - d);
                    float g = grow[(1 << d) - 1 + prefix];
                    int bit = (l >> (7 - d)) & 1;
                    p *= bit ? (1.0f - g) : g;
                }
                pv[s] = p;
            }
            acc[i][jp] = pack2(pv[0], pv[1]);   // reuse accumulators as staging
        }
    }
    __syncthreads();   // all reads of gates done before overwrite with leaf
    #pragma unroll
    for (int i = 0; i < 8; i++) {
        int r = ty * 8 + i;
        ulonglong2 s0, s1;
        s0.x = acc[i][0]; s0.y = acc[i][1];
        s1.x = acc[i][2]; s1.y = acc[i][3];
        *(ulonglong2*)&gl[r * GATES_P + tx * 8]     = s0;
        *(ulonglong2*)&gl[r * GATES_P + tx * 8 + 4] = s1;
    }

    // ---------------- Phase 3: out = leaf @ z^T ----------------
    #pragma unroll
    for (int i = 0; i < 8; i++)
        #pragma unroll
        for (int j = 0; j < 4; j++) acc[i][j] = 0ull;

    for (int lt = 0; lt < LEAVES / LC; lt++) {
        __syncthreads();
        // load zT tile [32][256] (coalesced read, conflict-free store)
        #pragma unroll 8
        for (int t = 0; t < 32; t++) {
            int idx = tid + t * NTHREADS;
            int lw = idx >> 8;
            int o  = idx & 255;
            zs[lw * OUT_F + o] = g_zT[(size_t)(lt * LC + lw) * OUT_F + o];
        }
        __syncthreads();
        #pragma unroll 8
        for (int lw = 0; lw < LC; lw++) {
            const ulonglong2* bp = (const ulonglong2*)&zs[lw * OUT_F + tx * 8];
            ulonglong2 b01 = bp[0];
            ulonglong2 b23 = bp[1];
            u64 b0 = b01.x, b1 = b01.y, b2 = b23.x, b3 = b23.y;
            #pragma unroll
            for (int i = 0; i < 8; i++) {
                u64 a2 = pack_dup(gl[(ty * 8 + i) * GATES_P + lt * LC + lw]);
                acc[i][0] = fma2(a2, b0, acc[i][0]);
                acc[i][1] = fma2(a2, b1, acc[i][1]);
                acc[i][2] = fma2(a2, b2, acc[i][2]);
                acc[i][3] = fma2(a2, b3, acc[i][3]);
            }
        }
    }

    // write output tile
    #pragma unroll
    for (int i = 0; i < 8; i++) {
        int r = rbase + ty * 8 + i;
        ulonglong2 s0, s1;
        s0.x = acc[i][0]; s0.y = acc[i][1];
        s1.x = acc[i][2]; s1.y = acc[i][3];
        *(ulonglong2*)&out[(size_t)r * OUT_F + tx * 8]     = s0;
        *(ulonglong2*)&out[(size_t)r * OUT_F + tx * 8 + 4] = s1;
    }
}

extern "C" void kernel_launch(void* const* d_in, const int* in_sizes, int n_in,
                              void* d_out, int out_size)
{
    const float* x  = (const float*)d_in[0];   // [B, 512]
    const float* gw = (const float*)d_in[1];   // [512, 255]
    const float* gb = (const float*)d_in[2];   // [255]
    const float* z  = (const float*)d_in[3];   // [256, 256]
    float* out = (float*)d_out;                // [B, 256]

    const int B = in_sizes[0] / IN_F;

    // transpose z -> g_zT (tiny, runs every call: deterministic & idempotent)
    transpose_z_kernel<<<(LEAVES * OUT_F) / 256, 256>>>(z);

    const int smem_bytes = SMEM_FLOATS * sizeof(float);
    cudaFuncSetAttribute(softtree_fused_kernel,
                         cudaFuncAttributeMaxDynamicSharedMemorySize, smem_bytes);
    softtree_fused_kernel<<<B / BM, NTHREADS, smem_bytes>>>(x, gw, gb, out);
}

// round 6
// speedup vs baseline: 3.8869x; 3.8869x over previous
#include <cuda_runtime.h>
#include <cstdint>

#define GATES 255
#define BM    128
#define NT    512

// Fragment-major, tf32-pre-rounded weights (rebuilt every call, deterministic).
__device__ float g_gwF[256 * 512];   // gates GEMM B: [n=gate 256][k 512]
__device__ float g_zF [256 * 256];   // out GEMM  B: [n=out 256][k=leaf 256]

// ---- smem layout (floats) ----
#define XA   0          // A frag tile [ra 8][ks 8][lane 32][4] = 8192
#define WSo  8192       // B frag tile [na 32][ks 8][lane 32][2] = 16384
#define GLo  24576      // gl [128][258] = 33024
#define GBSo 57600      // 256
#define SMEM_FLOATS 57856
#define GLS  258

__device__ __forceinline__ uint32_t f2tf32(float x) {
    uint32_t r; asm("cvt.rna.tf32.f32 %0, %1;" : "=r"(r) : "f"(x)); return r;
}
__device__ __forceinline__ void mma8(float* c, const uint32_t* a, uint32_t b0, uint32_t b1) {
    asm volatile("mma.sync.aligned.m16n8k8.row.col.f32.tf32.tf32.f32 "
        "{%0,%1,%2,%3}, {%4,%5,%6,%7}, {%8,%9}, {%0,%1,%2,%3};"
        : "+f"(c[0]), "+f"(c[1]), "+f"(c[2]), "+f"(c[3])
        : "r"(a[0]), "r"(a[1]), "r"(a[2]), "r"(a[3]), "r"(b0), "r"(b1));
}
__device__ __forceinline__ float sigmoidf_fast(float v) {
    return __fdividef(1.0f, 1.0f + __expf(-v));
}

// B fragment-major address for mma.m16n8k8 (k-tiles of 64):
// b0:(k=t, n=g) b1:(k=t+4, n=g), lane = (n&7)*4 + (k&3)
__device__ __forceinline__ int bfrag_addr(int k, int n) {
    return (k >> 6) * 16384 + (n >> 3) * 512 + ((k >> 3) & 7) * 64
         + ((n & 7) * 4 + (k & 3)) * 2 + ((k >> 2) & 1);
}

// ---- prep kernels ----
__global__ void prep_gw_kernel(const float* __restrict__ gw) {
    int idx = blockIdx.x * 256 + threadIdx.x;   // 131072
    int k = idx >> 8, n = idx & 255;
    float v = (n < GATES) ? gw[k * GATES + n] : 0.0f;
    g_gwF[bfrag_addr(k, n)] = __uint_as_float(f2tf32(v));
}
__global__ void prep_z_kernel(const float* __restrict__ z) {
    int idx = blockIdx.x * 256 + threadIdx.x;   // 65536
    int n = idx >> 8, k = idx & 255;
    g_zF[bfrag_addr(k, n)] = __uint_as_float(f2tf32(z[n * 256 + k]));
}

// ---- main fused kernel ----
extern "C" __global__ void __launch_bounds__(NT, 1)
softtree_mma_kernel(const float* __restrict__ x,
                    const float* __restrict__ gb,
                    float* __restrict__ out)
{
    extern __shared__ float smem[];
    float* gl  = smem + GLo;
    float* gbs = smem + GBSo;

    const int tid  = threadIdx.x;
    const int lane = tid & 31;
    const int wid  = tid >> 5;
    const int mg   = wid & 3;        // m-group: rows mg*32 .. +31
    const int ng   = wid >> 2;       // n-group: cols ng*64 .. +63
    const int g    = lane >> 2;      // group id within warp
    const int t    = lane & 3;       // thread-in-group
    const int rbase = blockIdx.x * BM;

    if (tid < 256) gbs[tid] = (tid < GATES) ? gb[tid] : 0.0f;

    float acc[2][8][4];
    #pragma unroll
    for (int ra = 0; ra < 2; ra++)
        #pragma unroll
        for (int j = 0; j < 8; j++)
            #pragma unroll
            for (int e = 0; e < 4; e++) acc[ra][j][e] = 0.0f;

    // ================= Phase 1: logits = x @ gwT =================
    for (int tk = 0; tk < 8; tk++) {
        __syncthreads();
        // fill A frag tile from x (tf32 round)
        #pragma unroll
        for (int i = 0; i < 4; i++) {
            int f = i * NT + tid;            // 0..2047
            int row = f >> 4, q = f & 15;
            const float4 v = *(const float4*)&x[(size_t)(rbase + row) * 512 + tk * 64 + q * 4];
            int base = XA + (row >> 4) * 1024 + (q >> 1) * 128 + (row & 7) * 16
                     + ((row >> 3) & 1) + 2 * (q & 1);
            smem[base + 0]  = __uint_as_float(f2tf32(v.x));
            smem[base + 4]  = __uint_as_float(f2tf32(v.y));
            smem[base + 8]  = __uint_as_float(f2tf32(v.z));
            smem[base + 12] = __uint_as_float(f2tf32(v.w));
        }
        // fill B frag tile (straight copy, already fragment-major)
        #pragma unroll
        for (int i = 0; i < 8; i++) {
            int q4 = i * NT + tid;           // 0..4095
            *(float4*)&smem[WSo + q4 * 4] = *(const float4*)&g_gwF[tk * 16384 + q4 * 4];
        }
        __syncthreads();
        #pragma unroll
        for (int ks = 0; ks < 8; ks++) {
            uint32_t a0[4], a1[4];
            *(uint4*)a0 = *(const uint4*)&smem[XA + (mg * 2)     * 1024 + ks * 128 + lane * 4];
            *(uint4*)a1 = *(const uint4*)&smem[XA + (mg * 2 + 1) * 1024 + ks * 128 + lane * 4];
            #pragma unroll
            for (int j = 0; j < 8; j++) {
                uint2 b = *(const uint2*)&smem[WSo + (ng * 8 + j) * 512 + ks * 64 + lane * 2];
                mma8(acc[0][j], a0, b.x, b.y);
                mma8(acc[1][j], a1, b.x, b.y);
            }
        }
    }

    // bias + sigmoid -> gl
    #pragma unroll
    for (int ra = 0; ra < 2; ra++)
        #pragma unroll
        for (int j = 0; j < 8; j++) {
            int row = mg * 32 + ra * 16 + g;
            int col = ng * 64 + j * 8 + 2 * t;
            float2 s0, s1;
            s0.x = sigmoidf_fast(acc[ra][j][0] + gbs[col]);
            s0.y = sigmoidf_fast(acc[ra][j][1] + gbs[col + 1]);
            s1.x = sigmoidf_fast(acc[ra][j][2] + gbs[col]);
            s1.y = sigmoidf_fast(acc[ra][j][3] + gbs[col + 1]);
            *(float2*)&gl[row * GLS + col]       = s0;
            *(float2*)&gl[(row + 8) * GLS + col] = s1;
        }
    __syncthreads();

    // ================= Middle: tree products =================
    {
        const int r = tid & 127;
        const int h = tid >> 7;              // leaf block h*64..h*64+63
        const float* grow = &gl[r * GLS];

        float p;
        { float g0 = grow[0];          p = (h >> 1) ? 1.0f - g0 : g0; }
        { float g1 = grow[1 + (h >> 1)]; p = (h & 1) ? p - p * g1 : p * g1; }
        float Q1[2];
        { float gg = grow[3 + h]; Q1[0] = p * gg; Q1[1] = p - Q1[0]; }
        float Q2[4];
        #pragma unroll
        for (int i = 0; i < 2; i++) {
            float gg = grow[7 + 2 * h + i];
            Q2[2 * i] = Q1[i] * gg; Q2[2 * i + 1] = Q1[i] - Q2[2 * i];
        }
        float Q3[8];
        #pragma unroll
        for (int i = 0; i < 4; i++) {
            float gg = grow[15 + 4 * h + i];
            Q3[2 * i] = Q2[i] * gg; Q3[2 * i + 1] = Q2[i] - Q3[2 * i];
        }
        float Q4[16];
        #pragma unroll
        for (int i = 0; i < 8; i++) {
            float gg = grow[31 + 8 * h + i];
            Q4[2 * i] = Q3[i] * gg; Q4[2 * i + 1] = Q3[i] - Q4[2 * i];
        }
        float Q5[32];
        #pragma unroll
        for (int i = 0; i < 16; i++) {
            float gg = grow[63 + 16 * h + i];
            Q5[2 * i] = Q4[i] * gg; Q5[2 * i + 1] = Q4[i] - Q5[2 * i];
        }
        float V[64];
        #pragma unroll
        for (int i = 0; i < 32; i++) {
            float gg = grow[127 + 32 * h + i];
            V[2 * i] = Q5[i] * gg; V[2 * i + 1] = Q5[i] - V[2 * i];
        }
        __syncthreads();                     // all gate reads done everywhere
        #pragma unroll
        for (int i = 0; i < 32; i++) {
            float2 w; w.x = V[2 * i]; w.y = V[2 * i + 1];
            *(float2*)&gl[r * GLS + h * 64 + 2 * i] = w;
        }
    }
    __syncthreads();

    // ================= Phase 3: out = leaf @ z^T =================
    #pragma unroll
    for (int ra = 0; ra < 2; ra++)
        #pragma unroll
        for (int j = 0; j < 8; j++)
            #pragma unroll
            for (int e = 0; e < 4; e++) acc[ra][j][e] = 0.0f;

    for (int tk = 0; tk < 4; tk++) {
        __syncthreads();
        // fill A frag tile from gl leaves (tf32 round)
        #pragma unroll
        for (int i = 0; i < 16; i++) {
            int idx = i * NT + tid;          // 0..8191
            int t4 = idx & 3;
            int row = (idx >> 2) & 127;
            int kh = idx >> 9;               // 0..15
            int kl = kh * 4 + t4;            // 0..63
            float v = gl[row * GLS + tk * 64 + kl];
            smem[XA + (row >> 4) * 1024 + (kl >> 3) * 128 + (row & 7) * 16 + t4 * 4
                 + ((row >> 3) & 1) + 2 * (kh & 1)] = __uint_as_float(f2tf32(v));
        }
        #pragma unroll
        for (int i = 0; i < 8; i++) {
            int q4 = i * NT + tid;
            *(float4*)&smem[WSo + q4 * 4] = *(const float4*)&g_zF[tk * 16384 + q4 * 4];
        }
        __syncthreads();
        #pragma unroll
        for (int ks = 0; ks < 8; ks++) {
            uint32_t a0[4], a1[4];
            *(uint4*)a0 = *(const uint4*)&smem[XA + (mg * 2)     * 1024 + ks * 128 + lane * 4];
            *(uint4*)a1 = *(const uint4*)&smem[XA + (mg * 2 + 1) * 1024 + ks * 128 + lane * 4];
            #pragma unroll
            for (int j = 0; j < 8; j++) {
                uint2 b = *(const uint2*)&smem[WSo + (ng * 8 + j) * 512 + ks * 64 + lane * 2];
                mma8(acc[0][j], a0, b.x, b.y);
                mma8(acc[1][j], a1, b.x, b.y);
            }
        }
    }

    // write out
    #pragma unroll
    for (int ra = 0; ra < 2; ra++)
        #pragma unroll
        for (int j = 0; j < 8; j++) {
            int row = rbase + mg * 32 + ra * 16 + g;
            int col = ng * 64 + j * 8 + 2 * t;
            float2 s0, s1;
            s0.x = acc[ra][j][0]; s0.y = acc[ra][j][1];
            s1.x = acc[ra][j][2]; s1.y = acc[ra][j][3];
            *(float2*)&out[(size_t)row * 256 + col]       = s0;
            *(float2*)&out[(size_t)(row + 8) * 256 + col] = s1;
        }
}

extern "C" void kernel_launch(void* const* d_in, const int* in_sizes, int n_in,
                              void* d_out, int out_size)
{
    const float* x  = (const float*)d_in[0];   // [B, 512]
    const float* gw = (const float*)d_in[1];   // [512, 255]
    const float* gb = (const float*)d_in[2];   // [255]
    const float* z  = (const float*)d_in[3];   // [256, 256]
    float* out = (float*)d_out;                // [B, 256]

    const int B = in_sizes[0] / 512;

    prep_gw_kernel<<<512, 256>>>(gw);
    prep_z_kernel<<<256, 256>>>(z);

    const int smem_bytes = SMEM_FLOATS * sizeof(float);
    cudaFuncSetAttribute(softtree_mma_kernel,
                         cudaFuncAttributeMaxDynamicSharedMemorySize, smem_bytes);
    softtree_mma_kernel<<<B / BM, NT, smem_bytes>>>(x, gb, out);
}

// round 7
// speedup vs baseline: 6.5466x; 1.6843x over previous
#include <cuda_runtime.h>
#include <cuda_fp16.h>
#include <cstdint>

#define GATES 255
#define BM    128
#define NT    512

// Fragment-major fp16 weights (rebuilt every call, deterministic).
__device__ __half g_gwH[512 * 256];   // gate GEMM B, 256KB: [k 512][n 256]
__device__ __half g_zH [256 * 256];   // out  GEMM B, 128KB: [k=leaf 256][n=out 256]

// ---- smem layout (bytes) ----
#define A_OFF(b)  ((b) * 16384u)              // A frag tile [128 m][64 k] fp16, x2
#define B_OFF(b)  (32768u + (b) * 32768u)     // B frag tile [256 n][64 k] fp16, x2
#define GL_OFF    98304u                      // gl [128][258] f32
#define GBS_OFF   230400u                     // 256 f32
#define SMEM_BYTES 231424u
#define GLS 258

// fragment-major half index for mma.m16n8k16 (k-tiles of 64):
// chunk (n8, ks) = 32 lanes x 2 b32; lane=(n&7)*4+((k>>1)&3), reg=(k>>3)&1, half=k&1
__host__ __device__ __forceinline__ int bidx16(int k, int n) {
    return (k >> 6) * 16384 + ((n >> 3) * 4 + ((k >> 4) & 3)) * 128
         + ((n & 7) * 4 + ((k >> 1) & 3)) * 4 + ((k >> 3) & 1) * 2 + (k & 1);
}

__device__ __forceinline__ uint32_t smem_u32(const void* p) {
    uint32_t a;
    asm("{ .reg .u64 t; cvta.to.shared.u64 t, %1; cvt.u32.u64 %0, t; }" : "=r"(a) : "l"(p));
    return a;
}
#define CP_ASYNC16(dst, src) \
    asm volatile("cp.async.cg.shared.global [%0], [%1], 16;" :: "r"(dst), "l"(src) : "memory")
#define CP_COMMIT() asm volatile("cp.async.commit_group;" ::: "memory")
#define CP_WAIT(n)  asm volatile("cp.async.wait_group %0;" :: "n"(n) : "memory")

__device__ __forceinline__ void mma16(float* c, const uint32_t* a, uint32_t b0, uint32_t b1) {
    asm volatile("mma.sync.aligned.m16n8k16.row.col.f32.f16.f16.f32 "
        "{%0,%1,%2,%3}, {%4,%5,%6,%7}, {%8,%9}, {%0,%1,%2,%3};"
        : "+f"(c[0]), "+f"(c[1]), "+f"(c[2]), "+f"(c[3])
        : "r"(a[0]), "r"(a[1]), "r"(a[2]), "r"(a[3]), "r"(b0), "r"(b1));
}
__device__ __forceinline__ float sigmoidf_fast(float v) {
    return __fdividef(1.0f, 1.0f + __expf(-v));
}

// ---- prep kernels ----
__global__ void prep_gw_kernel(const float* __restrict__ gw) {
    int idx = blockIdx.x * 256 + threadIdx.x;     // 131072
    int k = idx >> 8, n = idx & 255;
    float v = (n < GATES) ? gw[k * GATES + n] : 0.0f;
    g_gwH[bidx16(k, n)] = __float2half_rn(v);
}
__global__ void prep_z_kernel(const float* __restrict__ z) {
    int idx = blockIdx.x * 256 + threadIdx.x;     // 65536
    int n = idx >> 8, k = idx & 255;
    g_zH[bidx16(k, n)] = __float2half_rn(z[n * 256 + k]);
}

// A-frag STS address (bytes within A buffer) for float-quad (row, q), k0 = 4q
__device__ __forceinline__ uint32_t afrag_addr(int row, int q) {
    int ra = row >> 4, ks = q >> 2;
    int lane = (row & 7) * 4 + ((2 * q) & 3);
    int reg  = ((row >> 3) & 1) + 2 * ((q >> 1) & 1);
    return (uint32_t)((ra * 4 + ks) * 512 + lane * 16 + reg * 4);
}

// ---- main fused kernel ----
extern "C" __global__ void __launch_bounds__(NT, 1)
softtree_h2_kernel(const float* __restrict__ x,
                   const float* __restrict__ gb,
                   float* __restrict__ out)
{
    extern __shared__ char smc[];
    float* gl  = (float*)(smc + GL_OFF);
    float* gbs = (float*)(smc + GBS_OFF);
    const uint32_t sb = smem_u32(smc);

    const int tid  = threadIdx.x;
    const int lane = tid & 31;
    const int wid  = tid >> 5;
    const int mg   = wid & 3;
    const int ng   = wid >> 2;
    const int g    = lane >> 2;
    const int t4   = lane & 3;
    const int rbase = blockIdx.x * BM;

    if (tid < 256) gbs[tid] = (tid < GATES) ? gb[tid] : 0.0f;

    float acc[2][8][4];
    #pragma unroll
    for (int ra = 0; ra < 2; ra++)
        #pragma unroll
        for (int j = 0; j < 8; j++)
            #pragma unroll
            for (int e = 0; e < 4; e++) acc[ra][j][e] = 0.0f;

    uint32_t xh[8];   // prefetched A as half2 (4 float4 -> 8 half2)

    // helpers as lambdas (inlined)
    auto issueB = [&](int buf, const __half* srcTile) {
        const char* s = (const char*)srcTile;
        #pragma unroll
        for (int j = 0; j < 4; j++) {
            uint32_t off = (uint32_t)(tid + j * NT) * 16u;
            CP_ASYNC16(sb + B_OFF(buf) + off, s + off);
        }
    };
    auto ldgA = [&](int t) {
        #pragma unroll
        for (int j = 0; j < 4; j++) {
            int f = j * NT + tid;
            int row = f >> 4, q = f & 15;
            float4 v = *(const float4*)&x[(size_t)(rbase + row) * 512 + t * 64 + q * 4];
            xh[2 * j]     = __half2_raw(__floats2half2_rn(v.x, v.y)).x
                          | ((uint32_t)__half2_raw(__floats2half2_rn(v.x, v.y)).y << 16);
            // simpler: pack via intrinsic reinterpret
            __half2 h0 = __floats2half2_rn(v.x, v.y);
            __half2 h1 = __floats2half2_rn(v.z, v.w);
            xh[2 * j]     = *(uint32_t*)&h0;
            xh[2 * j + 1] = *(uint32_t*)&h1;
        }
    };
    auto stsA = [&](int buf) {
        #pragma unroll
        for (int j = 0; j < 4; j++) {
            int f = j * NT + tid;
            int row = f >> 4, q = f & 15;
            uint32_t a0 = afrag_addr(row, q);
            *(uint32_t*)(smc + A_OFF(buf) + a0)      = xh[2 * j];
            *(uint32_t*)(smc + A_OFF(buf) + a0 + 16) = xh[2 * j + 1];
        }
    };
    auto compute = [&](int buf) {
        #pragma unroll
        for (int ks = 0; ks < 4; ks++) {
            uint32_t a0[4], a1[4];
            *(uint4*)a0 = *(const uint4*)(smc + A_OFF(buf) + (uint32_t)(((mg * 2)     * 4 + ks) * 512 + lane * 16));
            *(uint4*)a1 = *(const uint4*)(smc + A_OFF(buf) + (uint32_t)(((mg * 2 + 1) * 4 + ks) * 512 + lane * 16));
            #pragma unroll
            for (int j = 0; j < 8; j++) {
                uint2 bb = *(const uint2*)(smc + B_OFF(buf) + (uint32_t)(((ng * 8 + j) * 4 + ks) * 256 + lane * 8));
                mma16(acc[0][j], a0, bb.x, bb.y);
                mma16(acc[1][j], a1, bb.x, bb.y);
            }
        }
    };

    // ================= Phase 1: logits = x @ gwT (8 K-tiles of 64) =================
    issueB(0, g_gwH);            CP_COMMIT();
    ldgA(0);  stsA(0);
    issueB(1, g_gwH + 16384);    CP_COMMIT();
    ldgA(1);
    CP_WAIT(1);
    __syncthreads();

    #pragma unroll 1
    for (int t = 0; t < 8; t++) {
        compute(t & 1);
        if (t < 7) stsA((t + 1) & 1);
        __syncthreads();
        if (t < 6) { issueB(t & 1, g_gwH + (size_t)(t + 2) * 16384); CP_COMMIT(); ldgA(t + 2); }
        if (t < 6) { CP_WAIT(1); } else { CP_WAIT(0); }
        __syncthreads();
    }

    // prefetch z tiles 0,1 (hidden behind middle phase)
    issueB(0, g_zH);          CP_COMMIT();
    issueB(1, g_zH + 16384);  CP_COMMIT();

    // ================= bias + sigmoid -> gl =================
    #pragma unroll
    for (int ra = 0; ra < 2; ra++)
        #pragma unroll
        for (int j = 0; j < 8; j++) {
            int row = mg * 32 + ra * 16 + g;
            int col = ng * 64 + j * 8 + 2 * t4;
            float2 s0, s1;
            s0.x = sigmoidf_fast(acc[ra][j][0] + gbs[col]);
            s0.y = sigmoidf_fast(acc[ra][j][1] + gbs[col + 1]);
            s1.x = sigmoidf_fast(acc[ra][j][2] + gbs[col]);
            s1.y = sigmoidf_fast(acc[ra][j][3] + gbs[col + 1]);
            *(float2*)&gl[row * GLS + col]       = s0;
            *(float2*)&gl[(row + 8) * GLS + col] = s1;
        }
    __syncthreads();

    // ================= tree products =================
    {
        const int r = tid & 127;
        const int h = tid >> 7;
        const float* grow = &gl[r * GLS];

        float p;
        { float g0 = grow[0];            p = (h >> 1) ? 1.0f - g0 : g0; }
        { float g1 = grow[1 + (h >> 1)]; p = (h & 1) ? p - p * g1 : p * g1; }
        float Q1[2];
        { float gg = grow[3 + h]; Q1[0] = p * gg; Q1[1] = p - Q1[0]; }
        float Q2[4];
        #pragma unroll
        for (int i = 0; i < 2; i++) {
            float gg = grow[7 + 2 * h + i];
            Q2[2 * i] = Q1[i] * gg; Q2[2 * i + 1] = Q1[i] - Q2[2 * i];
        }
        float Q3[8];
        #pragma unroll
        for (int i = 0; i < 4; i++) {
            float gg = grow[15 + 4 * h + i];
            Q3[2 * i] = Q2[i] * gg; Q3[2 * i + 1] = Q2[i] - Q3[2 * i];
        }
        float Q4[16];
        #pragma unroll
        for (int i = 0; i < 8; i++) {
            float gg = grow[31 + 8 * h + i];
            Q4[2 * i] = Q3[i] * gg; Q4[2 * i + 1] = Q3[i] - Q4[2 * i];
        }
        float Q5[32];
        #pragma unroll
        for (int i = 0; i < 16; i++) {
            float gg = grow[63 + 16 * h + i];
            Q5[2 * i] = Q4[i] * gg; Q5[2 * i + 1] = Q4[i] - Q5[2 * i];
        }
        float V[64];
        #pragma unroll
        for (int i = 0; i < 32; i++) {
            float gg = grow[127 + 32 * h + i];
            V[2 * i] = Q5[i] * gg; V[2 * i + 1] = Q5[i] - V[2 * i];
        }
        __syncthreads();
        #pragma unroll
        for (int i = 0; i < 32; i++) {
            float2 w; w.x = V[2 * i]; w.y = V[2 * i + 1];
            *(float2*)&gl[r * GLS + h * 64 + 2 * i] = w;
        }
    }
    __syncthreads();

    // ================= Phase 3: out = leaf @ z^T (4 K-tiles of 64) =================
    #pragma unroll
    for (int ra = 0; ra < 2; ra++)
        #pragma unroll
        for (int j = 0; j < 8; j++)
            #pragma unroll
            for (int e = 0; e < 4; e++) acc[ra][j][e] = 0.0f;

    auto fillA3 = [&](int t, int buf) {
        #pragma unroll
        for (int j = 0; j < 4; j++) {
            int f = j * NT + tid;
            int row = f >> 4, q = f & 15;
            float2 u0 = *(const float2*)&gl[row * GLS + t * 64 + q * 4];
            float2 u1 = *(const float2*)&gl[row * GLS + t * 64 + q * 4 + 2];
            __half2 h0 = __floats2half2_rn(u0.x, u0.y);
            __half2 h1 = __floats2half2_rn(u1.x, u1.y);
            uint32_t a0 = afrag_addr(row, q);
            *(uint32_t*)(smc + A_OFF(buf) + a0)      = *(uint32_t*)&h0;
            *(uint32_t*)(smc + A_OFF(buf) + a0 + 16) = *(uint32_t*)&h1;
        }
    };

    fillA3(0, 0);
    CP_WAIT(1);
    __syncthreads();

    #pragma unroll 1
    for (int t = 0; t < 4; t++) {
        compute(t & 1);
        if (t < 3) fillA3(t + 1, (t + 1) & 1);
        __syncthreads();
        if (t < 2) { issueB(t & 1, g_zH + (size_t)(t + 2) * 16384); CP_COMMIT(); }
        if (t < 2) { CP_WAIT(1); } else { CP_WAIT(0); }
        __syncthreads();
    }

    // ================= write out =================
    #pragma unroll
    for (int ra = 0; ra < 2; ra++)
        #pragma unroll
        for (int j = 0; j < 8; j++) {
            int row = rbase + mg * 32 + ra * 16 + g;
            int col = ng * 64 + j * 8 + 2 * t4;
            float2 s0, s1;
            s0.x = acc[ra][j][0]; s0.y = acc[ra][j][1];
            s1.x = acc[ra][j][2]; s1.y = acc[ra][j][3];
            *(float2*)&out[(size_t)row * 256 + col]       = s0;
            *(float2*)&out[(size_t)(row + 8) * 256 + col] = s1;
        }
}

extern "C" void kernel_launch(void* const* d_in, const int* in_sizes, int n_in,
                              void* d_out, int out_size)
{
    const float* x  = (const float*)d_in[0];   // [B, 512]
    const float* gw = (const float*)d_in[1];   // [512, 255]
    const float* gb = (const float*)d_in[2];   // [255]
    const float* z  = (const float*)d_in[3];   // [256, 256]
    float* out = (float*)d_out;                // [B, 256]

    const int B = in_sizes[0] / 512;

    prep_gw_kernel<<<512, 256>>>(gw);
    prep_z_kernel<<<256, 256>>>(z);

    cudaFuncSetAttribute(softtree_h2_kernel,
                         cudaFuncAttributeMaxDynamicSharedMemorySize, SMEM_BYTES);
    softtree_h2_kernel<<<B / BM, NT, SMEM_BYTES>>>(x, gb, out);
}

// round 8
// speedup vs baseline: 6.7163x; 1.0259x over previous
#include <cuda_runtime.h>
#include <cuda_fp16.h>
#include <cstdint>

#define GATES 255
#define BM    64
#define NT    512

// Fragment-major fp16 weights (rebuilt every call, deterministic).
__device__ __half g_gwH[512 * 256];   // gate GEMM B: tiles of [64k][256n]
__device__ __half g_zH [256 * 256];   // out  GEMM B: tiles of [64k][256n]

// ---- smem layout (bytes) ----
#define A_OFF(b)   ((unsigned)(b) * 8192u)              // A frag [64m][64k] fp16, x2
#define B_OFF(b)   (16384u + (unsigned)(b) * 32768u)    // B frag [256n][64k] fp16, x3
#define GL_OFF     114688u                              // gl [64][258] f32
#define GBS_OFF    180736u                              // 256 f32
#define SMEM_BYTES 181760u
#define GLS 258

// fragment-major half index for mma.m16n8k16 (k-tiles of 64)
__host__ __device__ __forceinline__ int bidx16(int k, int n) {
    return (k >> 6) * 16384 + ((n >> 3) * 4 + ((k >> 4) & 3)) * 128
         + ((n & 7) * 4 + ((k >> 1) & 3)) * 4 + ((k >> 3) & 1) * 2 + (k & 1);
}

__device__ __forceinline__ uint32_t smem_u32(const void* p) {
    uint32_t a;
    asm("{ .reg .u64 t; cvta.to.shared.u64 t, %1; cvt.u32.u64 %0, t; }" : "=r"(a) : "l"(p));
    return a;
}
#define CP_ASYNC16(dst, src) \
    asm volatile("cp.async.cg.shared.global [%0], [%1], 16;" :: "r"(dst), "l"(src) : "memory")
#define CP_COMMIT() asm volatile("cp.async.commit_group;" ::: "memory")
#define CP_WAIT(n)  asm volatile("cp.async.wait_group %0;" :: "n"(n) : "memory")

__device__ __forceinline__ void mma16(float* c, const uint32_t* a, uint32_t b0, uint32_t b1) {
    asm volatile("mma.sync.aligned.m16n8k16.row.col.f32.f16.f16.f32 "
        "{%0,%1,%2,%3}, {%4,%5,%6,%7}, {%8,%9}, {%0,%1,%2,%3};"
        : "+f"(c[0]), "+f"(c[1]), "+f"(c[2]), "+f"(c[3])
        : "r"(a[0]), "r"(a[1]), "r"(a[2]), "r"(a[3]), "r"(b0), "r"(b1));
}
__device__ __forceinline__ float sigmoidf_fast(float v) {
    return __fdividef(1.0f, 1.0f + __expf(-v));
}

// A-frag STS address (bytes) for float-quad (row, q): covers k = 4q..4q+3
__device__ __forceinline__ uint32_t afrag_addr(int row, int q) {
    int ra = row >> 4, ks = q >> 2;
    int lane = (row & 7) * 4 + ((2 * q) & 3);
    int reg  = ((row >> 3) & 1) + 2 * ((q >> 1) & 1);
    return (uint32_t)((ra * 4 + ks) * 512 + lane * 16 + reg * 4);
}

// ---- merged prep kernel (1 launch -> ncu -s 5 lands on the MAIN kernel) ----
__global__ void prep_kernel(const float* __restrict__ gw, const float* __restrict__ z) {
    int b = blockIdx.x;
    if (b < 512) {
        int idx = b * 256 + threadIdx.x;            // 131072
        int k = idx >> 8, n = idx & 255;
        float v = (n < GATES) ? gw[k * GATES + n] : 0.0f;
        g_gwH[bidx16(k, n)] = __float2half_rn(v);
    } else {
        int idx = (b - 512) * 256 + threadIdx.x;    // 65536
        int n = idx >> 8, k = idx & 255;
        g_zH[bidx16(k, n)] = __float2half_rn(z[n * 256 + k]);
    }
}

// ---- main fused kernel: one CTA = 64 rows ----
extern "C" __global__ void __launch_bounds__(NT, 1)
softtree_h3_kernel(const float* __restrict__ x,
                   const float* __restrict__ gb,
                   float* __restrict__ out)
{
    extern __shared__ char smc[];
    float* gl  = (float*)(smc + GL_OFF);
    float* gbs = (float*)(smc + GBS_OFF);
    const uint32_t sb = smem_u32(smc);

    const int tid  = threadIdx.x;
    const int lane = tid & 31;
    const int wid  = tid >> 5;
    const int mg   = wid & 1;        // rows mg*32 .. +31
    const int ng   = wid >> 1;       // cols ng*32 .. +31
    const int g    = lane >> 2;
    const int t4   = lane & 3;
    const int rbase = blockIdx.x * BM;

    if (tid < 256) gbs[tid] = (tid < GATES) ? gb[tid] : 0.0f;

    float acc[2][4][4];
    #pragma unroll
    for (int ra = 0; ra < 2; ra++)
        #pragma unroll
        for (int j = 0; j < 4; j++)
            #pragma unroll
            for (int e = 0; e < 4; e++) acc[ra][j][e] = 0.0f;

    uint32_t xh[4];

    auto issueB = [&](int buf, const __half* srcTile) {
        const char* s = (const char*)srcTile;
        #pragma unroll
        for (int j = 0; j < 4; j++) {
            uint32_t off = (uint32_t)(tid + j * NT) * 16u;
            CP_ASYNC16(sb + B_OFF(buf) + off, s + off);
        }
    };
    auto ldgA = [&](int t) {
        #pragma unroll
        for (int j = 0; j < 2; j++) {
            int f = j * NT + tid;            // 0..1023
            int row = f >> 4, q = f & 15;
            float4 v = *(const float4*)&x[(size_t)(rbase + row) * 512 + t * 64 + q * 4];
            __half2 h0 = __floats2half2_rn(v.x, v.y);
            __half2 h1 = __floats2half2_rn(v.z, v.w);
            xh[2 * j]     = *(uint32_t*)&h0;
            xh[2 * j + 1] = *(uint32_t*)&h1;
        }
    };
    auto stsA = [&](int buf) {
        #pragma unroll
        for (int j = 0; j < 2; j++) {
            int f = j * NT + tid;
            int row = f >> 4, q = f & 15;
            uint32_t a0 = afrag_addr(row, q);
            *(uint32_t*)(smc + A_OFF(buf) + a0)      = xh[2 * j];
            *(uint32_t*)(smc + A_OFF(buf) + a0 + 16) = xh[2 * j + 1];
        }
    };
    auto compute = [&](int ab, int bb) {
        #pragma unroll
        for (int ks = 0; ks < 4; ks++) {
            uint32_t a0[4], a1[4];
            *(uint4*)a0 = *(const uint4*)(smc + A_OFF(ab) + (uint32_t)(((mg * 2)     * 4 + ks) * 512 + lane * 16));
            *(uint4*)a1 = *(const uint4*)(smc + A_OFF(ab) + (uint32_t)(((mg * 2 + 1) * 4 + ks) * 512 + lane * 16));
            #pragma unroll
            for (int j = 0; j < 4; j++) {
                uint2 bv = *(const uint2*)(smc + B_OFF(bb) + (uint32_t)(((ng * 4 + j) * 4 + ks) * 256 + lane * 8));
                mma16(acc[0][j], a0, bv.x, bv.y);
                mma16(acc[1][j], a1, bv.x, bv.y);
            }
        }
    };

    // ============ Phase 1: logits = x @ gwT (8 K-tiles, 3 B bufs, 1 sync/iter) ============
    issueB(0, g_gwH);            CP_COMMIT();
    issueB(1, g_gwH + 16384);    CP_COMMIT();
    ldgA(0);  stsA(0);
    issueB(2, g_gwH + 32768);    CP_COMMIT();
    ldgA(1);

    #pragma unroll 1
    for (int t = 0; t < 8; t++) {
        if (t == 0)      { CP_WAIT(2); }
        else if (t < 7)  { CP_WAIT(1); }
        else             { CP_WAIT(0); }
        __syncthreads();
        if (t >= 1 && t <= 5) { issueB((t + 2) % 3, g_gwH + (size_t)(t + 2) * 16384); CP_COMMIT(); }
        compute(t & 1, t % 3);
        if (t < 7) stsA((t + 1) & 1);
        if (t < 6) ldgA(t + 2);
    }
    __syncthreads();   // retire compute(7) everywhere before reusing B bufs

    // prefetch z tiles 0,1 (latency hidden behind the middle phase)
    issueB(0, g_zH);          CP_COMMIT();
    issueB(1, g_zH + 16384);  CP_COMMIT();

    // ============ bias + sigmoid -> gl ============
    #pragma unroll
    for (int ra = 0; ra < 2; ra++)
        #pragma unroll
        for (int j = 0; j < 4; j++) {
            int row = mg * 32 + ra * 16 + g;
            int col = ng * 32 + j * 8 + 2 * t4;
            float2 s0, s1;
            s0.x = sigmoidf_fast(acc[ra][j][0] + gbs[col]);
            s0.y = sigmoidf_fast(acc[ra][j][1] + gbs[col + 1]);
            s1.x = sigmoidf_fast(acc[ra][j][2] + gbs[col]);
            s1.y = sigmoidf_fast(acc[ra][j][3] + gbs[col + 1]);
            *(float2*)&gl[row * GLS + col]       = s0;
            *(float2*)&gl[(row + 8) * GLS + col] = s1;
        }
    __syncthreads();

    // ============ tree products: thread = (row r, 32-leaf block h8) ============
    {
        const int r  = tid & 63;
        const int h8 = tid >> 6;             // 0..7, leaves h8*32 .. +31
        const float* grow = &gl[r * GLS];

        float p;
        { float g0 = grow[0];             p = (h8 >> 2) ? 1.0f - g0 : g0; }
        { float g1 = grow[1 + (h8 >> 2)]; p = ((h8 >> 1) & 1) ? p - p * g1 : p * g1; }
        { float g2 = grow[3 + (h8 >> 1)]; p = (h8 & 1) ? p - p * g2 : p * g2; }
        float Q1[2];
        { float gg = grow[7 + h8]; Q1[0] = p * gg; Q1[1] = p - Q1[0]; }
        float Q2[4];
        #pragma unroll
        for (int i = 0; i < 2; i++) {
            float gg = grow[15 + 2 * h8 + i];
            Q2[2 * i] = Q1[i] * gg; Q2[2 * i + 1] = Q1[i] - Q2[2 * i];
        }
        float Q3[8];
        #pragma unroll
        for (int i = 0; i < 4; i++) {
            float gg = grow[31 + 4 * h8 + i];
            Q3[2 * i] = Q2[i] * gg; Q3[2 * i + 1] = Q2[i] - Q3[2 * i];
        }
        float Q4[16];
        #pragma unroll
        for (int i = 0; i < 8; i++) {
            float gg = grow[63 + 8 * h8 + i];
            Q4[2 * i] = Q3[i] * gg; Q4[2 * i + 1] = Q3[i] - Q4[2 * i];
        }
        float V[32];
        #pragma unroll
        for (int i = 0; i < 16; i++) {
            float gg = grow[127 + 16 * h8 + i];
            V[2 * i] = Q4[i] * gg; V[2 * i + 1] = Q4[i] - V[2 * i];
        }
        __syncthreads();                     // all gate reads retired before overwrite
        #pragma unroll
        for (int i = 0; i < 16; i++) {
            float2 w; w.x = V[2 * i]; w.y = V[2 * i + 1];
            *(float2*)&gl[r * GLS + h8 * 32 + 2 * i] = w;
        }
    }
    __syncthreads();

    // ============ Phase 3: out = leaf @ z^T (4 K-tiles) ============
    #pragma unroll
    for (int ra = 0; ra < 2; ra++)
        #pragma unroll
        for (int j = 0; j < 4; j++)
            #pragma unroll
            for (int e = 0; e < 4; e++) acc[ra][j][e] = 0.0f;

    auto fillA3 = [&](int t, int buf) {
        #pragma unroll
        for (int j = 0; j < 2; j++) {
            int f = j * NT + tid;
            int row = f >> 4, q = f & 15;
            float2 u0 = *(const float2*)&gl[row * GLS + t * 64 + q * 4];
            float2 u1 = *(const float2*)&gl[row * GLS + t * 64 + q * 4 + 2];
            __half2 h0 = __floats2half2_rn(u0.x, u0.y);
            __half2 h1 = __floats2half2_rn(u1.x, u1.y);
            uint32_t a0 = afrag_addr(row, q);
            *(uint32_t*)(smc + A_OFF(buf) + a0)      = *(uint32_t*)&h0;
            *(uint32_t*)(smc + A_OFF(buf) + a0 + 16) = *(uint32_t*)&h1;
        }
    };

    fillA3(0, 0);

    #pragma unroll 1
    for (int t = 0; t < 4; t++) {
        if (t < 3) { CP_WAIT(1); } else { CP_WAIT(0); }
        __syncthreads();
        if (t < 2) { issueB((t + 2) % 3, g_zH + (size_t)(t + 2) * 16384); CP_COMMIT(); }
        compute(t & 1, t % 3);
        if (t < 3) fillA3(t + 1, (t + 1) & 1);
    }

    // ============ write out ============
    #pragma unroll
    for (int ra = 0; ra < 2; ra++)
        #pragma unroll
        for (int j = 0; j < 4; j++) {
            int row = rbase + mg * 32 + ra * 16 + g;
            int col = ng * 32 + j * 8 + 2 * t4;
            float2 s0, s1;
            s0.x = acc[ra][j][0]; s0.y = acc[ra][j][1];
            s1.x = acc[ra][j][2]; s1.y = acc[ra][j][3];
            *(float2*)&out[(size_t)row * 256 + col]       = s0;
            *(float2*)&out[(size_t)(row + 8) * 256 + col] = s1;
        }
}

extern "C" void kernel_launch(void* const* d_in, const int* in_sizes, int n_in,
                              void* d_out, int out_size)
{
    const float* x  = (const float*)d_in[0];   // [B, 512]
    const float* gw = (const float*)d_in[1];   // [512, 255]
    const float* gb = (const float*)d_in[2];   // [255]
    const float* z  = (const float*)d_in[3];   // [256, 256]
    float* out = (float*)d_out;                // [B, 256]

    const int B = in_sizes[0] / 512;

    prep_kernel<<<768, 256>>>(gw, z);

    cudaFuncSetAttribute(softtree_h3_kernel,
                         cudaFuncAttributeMaxDynamicSharedMemorySize, SMEM_BYTES);
    softtree_h3_kernel<<<B / BM, NT, SMEM_BYTES>>>(x, gb, out);
}

// round 9
// speedup vs baseline: 8.2501x; 1.2284x over previous
#include <cuda_runtime.h>
#include <cuda_fp16.h>
#include <cstdint>

#define GATES 255
#define BM    64
#define NT    512

// Fragment-major fp16 weights (rebuilt every call, deterministic).
__device__ __half g_gwH[512 * 256];   // gate GEMM B: tiles of [64k][256n]
__device__ __half g_zH [256 * 256];   // out  GEMM B: tiles of [64k][256n]

// ---- smem layout (bytes). gates(f32) overlaps A+B bufs (disjoint lifetimes).
#define A_OFF      0u                                  // A frag [64m][64k] fp16 (8KB, single buf)
#define B_OFF(b)   (8192u + (unsigned)(b) * 32768u)    // B frag [256n][64k] fp16, x2
#define GATES_OFF  0u                                  // gates [64][257] f32 (65792B <= 73728)
#define LEAF_OFF   73728u                              // leaf  [64][260] fp16 (33280B)
#define GBS_OFF    107008u                             // 256 f32
#define SMEM_BYTES 108032u
#define GGLS 257
#define LLS  260

// fragment-major half index for mma.m16n8k16 (k-tiles of 64)
__host__ __device__ __forceinline__ int bidx16(int k, int n) {
    return (k >> 6) * 16384 + ((n >> 3) * 4 + ((k >> 4) & 3)) * 128
         + ((n & 7) * 4 + ((k >> 1) & 3)) * 4 + ((k >> 3) & 1) * 2 + (k & 1);
}

__device__ __forceinline__ uint32_t smem_u32(const void* p) {
    uint32_t a;
    asm("{ .reg .u64 t; cvta.to.shared.u64 t, %1; cvt.u32.u64 %0, t; }" : "=r"(a) : "l"(p));
    return a;
}
#define CP_ASYNC16(dst, src) \
    asm volatile("cp.async.cg.shared.global [%0], [%1], 16;" :: "r"(dst), "l"(src) : "memory")
#define CP_COMMIT() asm volatile("cp.async.commit_group;" ::: "memory")
#define CP_WAIT(n)  asm volatile("cp.async.wait_group %0;" :: "n"(n) : "memory")

__device__ __forceinline__ void mma16(float* c, const uint32_t* a, uint32_t b0, uint32_t b1) {
    asm volatile("mma.sync.aligned.m16n8k16.row.col.f32.f16.f16.f32 "
        "{%0,%1,%2,%3}, {%4,%5,%6,%7}, {%8,%9}, {%0,%1,%2,%3};"
        : "+f"(c[0]), "+f"(c[1]), "+f"(c[2]), "+f"(c[3])
        : "r"(a[0]), "r"(a[1]), "r"(a[2]), "r"(a[3]), "r"(b0), "r"(b1));
}
__device__ __forceinline__ float sigmoidf_fast(float v) {
    return __fdividef(1.0f, 1.0f + __expf(-v));
}

// A-frag STS address (bytes) for float-quad (row, q): covers k = 4q..4q+3
__device__ __forceinline__ uint32_t afrag_addr(int row, int q) {
    int ra = row >> 4, ks = q >> 2;
    int lane = (row & 7) * 4 + ((2 * q) & 3);
    int reg  = ((row >> 3) & 1) + 2 * ((q >> 1) & 1);
    return (uint32_t)((ra * 4 + ks) * 512 + lane * 16 + reg * 4);
}

// ---- merged prep kernel ----
__global__ void prep_kernel(const float* __restrict__ gw, const float* __restrict__ z) {
    int b = blockIdx.x;
    if (b < 512) {
        int idx = b * 256 + threadIdx.x;            // 131072
        int k = idx >> 8, n = idx & 255;
        float v = (n < GATES) ? gw[k * GATES + n] : 0.0f;
        g_gwH[bidx16(k, n)] = __float2half_rn(v);
    } else {
        int idx = (b - 512) * 256 + threadIdx.x;    // 65536
        int n = idx >> 8, k = idx & 255;
        g_zH[bidx16(k, n)] = __float2half_rn(z[n * 256 + k]);
    }
}

// ---- main fused kernel: one CTA = 64 rows, 2 CTAs/SM ----
extern "C" __global__ void __launch_bounds__(NT, 2)
softtree_h4_kernel(const float* __restrict__ x,
                   const float* __restrict__ gb,
                   float* __restrict__ out)
{
    extern __shared__ char smc[];
    float*  gates = (float*)(smc + GATES_OFF);
    __half* leaf  = (__half*)(smc + LEAF_OFF);
    float*  gbs   = (float*)(smc + GBS_OFF);
    const uint32_t sb = smem_u32(smc);

    const int tid  = threadIdx.x;
    const int lane = tid & 31;
    const int wid  = tid >> 5;
    const int mg   = wid & 1;        // rows mg*32 .. +31
    const int ng   = wid >> 1;       // cols ng*32 .. +31
    const int g    = lane >> 2;
    const int t4   = lane & 3;
    const int rbase = blockIdx.x * BM;

    if (tid < 256) gbs[tid] = (tid < GATES) ? gb[tid] : 0.0f;

    float acc[2][4][4];
    #pragma unroll
    for (int ra = 0; ra < 2; ra++)
        #pragma unroll
        for (int j = 0; j < 4; j++)
            #pragma unroll
            for (int e = 0; e < 4; e++) acc[ra][j][e] = 0.0f;

    uint32_t xh[4];

    auto issueB = [&](int buf, const __half* srcTile) {
        const char* s = (const char*)srcTile;
        #pragma unroll
        for (int j = 0; j < 4; j++) {
            uint32_t off = (uint32_t)(tid + j * NT) * 16u;
            CP_ASYNC16(sb + B_OFF(buf) + off, s + off);
        }
    };
    auto ldgA = [&](int t) {
        #pragma unroll
        for (int j = 0; j < 2; j++) {
            int f = j * NT + tid;
            int row = f >> 4, q = f & 15;
            float4 v = *(const float4*)&x[(size_t)(rbase + row) * 512 + t * 64 + q * 4];
            __half2 h0 = __floats2half2_rn(v.x, v.y);
            __half2 h1 = __floats2half2_rn(v.z, v.w);
            xh[2 * j]     = *(uint32_t*)&h0;
            xh[2 * j + 1] = *(uint32_t*)&h1;
        }
    };
    auto stsA = [&]() {
        #pragma unroll
        for (int j = 0; j < 2; j++) {
            int f = j * NT + tid;
            int row = f >> 4, q = f & 15;
            uint32_t a0 = afrag_addr(row, q);
            *(uint32_t*)(smc + A_OFF + a0)      = xh[2 * j];
            *(uint32_t*)(smc + A_OFF + a0 + 16) = xh[2 * j + 1];
        }
    };
    auto compute = [&](int bb) {
        #pragma unroll
        for (int ks = 0; ks < 4; ks++) {
            uint32_t a0[4], a1[4];
            *(uint4*)a0 = *(const uint4*)(smc + A_OFF + (uint32_t)(((mg * 2)     * 4 + ks) * 512 + lane * 16));
            *(uint4*)a1 = *(const uint4*)(smc + A_OFF + (uint32_t)(((mg * 2 + 1) * 4 + ks) * 512 + lane * 16));
            #pragma unroll
            for (int j = 0; j < 4; j++) {
                uint2 bv = *(const uint2*)(smc + B_OFF(bb) + (uint32_t)(((ng * 4 + j) * 4 + ks) * 256 + lane * 8));
                mma16(acc[0][j], a0, bv.x, bv.y);
                mma16(acc[1][j], a1, bv.x, bv.y);
            }
        }
    };

    // ============ Phase 1: logits = x @ gwT (8 K-tiles, B 2-buf, A 1-buf) ============
    issueB(0, g_gwH);           CP_COMMIT();
    issueB(1, g_gwH + 16384);   CP_COMMIT();
    ldgA(0);  stsA();  ldgA(1);

    #pragma unroll 1
    for (int t = 0; t < 8; t++) {
        if (t < 7) { CP_WAIT(1); } else { CP_WAIT(0); }
        __syncthreads();
        compute(t & 1);
        __syncthreads();
        if (t <= 5) { issueB(t & 1, g_gwH + (size_t)(t + 2) * 16384); CP_COMMIT(); }
        if (t < 7) { stsA(); if (t < 6) ldgA(t + 2); }
    }

    // ============ bias + sigmoid -> gates (f32, overlapping A/B region) ============
    #pragma unroll
    for (int ra = 0; ra < 2; ra++)
        #pragma unroll
        for (int j = 0; j < 4; j++) {
            int row = mg * 32 + ra * 16 + g;
            int col = ng * 32 + j * 8 + 2 * t4;
            gates[row * GGLS + col]           = sigmoidf_fast(acc[ra][j][0] + gbs[col]);
            gates[row * GGLS + col + 1]       = sigmoidf_fast(acc[ra][j][1] + gbs[col + 1]);
            gates[(row + 8) * GGLS + col]     = sigmoidf_fast(acc[ra][j][2] + gbs[col]);
            gates[(row + 8) * GGLS + col + 1] = sigmoidf_fast(acc[ra][j][3] + gbs[col + 1]);
        }
    __syncthreads();

    // ============ tree products -> leaf fp16 (streamed, low register pressure) ============
    {
        const int r  = tid & 63;
        const int h8 = tid >> 6;             // leaves h8*32 .. +31
        const float* grow = &gates[r * GGLS];

        float p;
        { float g0 = grow[0];             p = (h8 >> 2) ? 1.0f - g0 : g0; }
        { float g1 = grow[1 + (h8 >> 2)]; p = ((h8 >> 1) & 1) ? p - p * g1 : p * g1; }
        { float g2 = grow[3 + (h8 >> 1)]; p = (h8 & 1) ? p - p * g2 : p * g2; }
        float Q1[2];
        { float gg = grow[7 + h8]; Q1[0] = p * gg; Q1[1] = p - Q1[0]; }
        float Q2[4];
        #pragma unroll
        for (int i = 0; i < 2; i++) {
            float gg = grow[15 + 2 * h8 + i];
            Q2[2 * i] = Q1[i] * gg; Q2[2 * i + 1] = Q1[i] - Q2[2 * i];
        }
        float Q3[8];
        #pragma unroll
        for (int i = 0; i < 4; i++) {
            float gg = grow[31 + 4 * h8 + i];
            Q3[2 * i] = Q2[i] * gg; Q3[2 * i + 1] = Q2[i] - Q3[2 * i];
        }
        __half* lrow = &leaf[r * LLS + h8 * 32];
        #pragma unroll
        for (int i = 0; i < 8; i++) {
            float gg = grow[63 + 8 * h8 + i];
            float qa = Q3[i] * gg, qb = Q3[i] - qa;
            float g5a = grow[127 + 16 * h8 + 2 * i];
            float v0 = qa * g5a, v1 = qa - v0;
            *(__half2*)&lrow[4 * i] = __floats2half2_rn(v0, v1);
            float g5b = grow[127 + 16 * h8 + 2 * i + 1];
            float v2 = qb * g5b, v3 = qb - v2;
            *(__half2*)&lrow[4 * i + 2] = __floats2half2_rn(v2, v3);
        }
    }
    __syncthreads();   // gates reads retired; A/B region free for phase 3

    // ============ Phase 3: out = leaf @ z^T (4 K-tiles) ============
    #pragma unroll
    for (int ra = 0; ra < 2; ra++)
        #pragma unroll
        for (int j = 0; j < 4; j++)
            #pragma unroll
            for (int e = 0; e < 4; e++) acc[ra][j][e] = 0.0f;

    auto fillA = [&](int t) {
        #pragma unroll
        for (int j = 0; j < 2; j++) {
            int f = j * NT + tid;
            int row = f >> 4, q = f & 15;
            uint2 u = *(const uint2*)&leaf[row * LLS + t * 64 + q * 4];
            uint32_t a0 = afrag_addr(row, q);
            *(uint32_t*)(smc + A_OFF + a0)      = u.x;
            *(uint32_t*)(smc + A_OFF + a0 + 16) = u.y;
        }
    };

    issueB(0, g_zH);           CP_COMMIT();
    issueB(1, g_zH + 16384);   CP_COMMIT();
    fillA(0);

    #pragma unroll 1
    for (int t = 0; t < 4; t++) {
        if (t < 3) { CP_WAIT(1); } else { CP_WAIT(0); }
        __syncthreads();
        compute(t & 1);
        __syncthreads();
        if (t <= 1) { issueB(t & 1, g_zH + (size_t)(t + 2) * 16384); CP_COMMIT(); }
        if (t < 3) fillA(t + 1);
    }

    // ============ write out ============
    #pragma unroll
    for (int ra = 0; ra < 2; ra++)
        #pragma unroll
        for (int j = 0; j < 4; j++) {
            int row = rbase + mg * 32 + ra * 16 + g;
            int col = ng * 32 + j * 8 + 2 * t4;
            float2 s0, s1;
            s0.x = acc[ra][j][0]; s0.y = acc[ra][j][1];
            s1.x = acc[ra][j][2]; s1.y = acc[ra][j][3];
            *(float2*)&out[(size_t)row * 256 + col]       = s0;
            *(float2*)&out[(size_t)(row + 8) * 256 + col] = s1;
        }
}

extern "C" void kernel_launch(void* const* d_in, const int* in_sizes, int n_in,
                              void* d_out, int out_size)
{
    const float* x  = (const float*)d_in[0];   // [B, 512]
    const float* gw = (const float*)d_in[1];   // [512, 255]
    const float* gb = (const float*)d_in[2];   // [255]
    const float* z  = (const float*)d_in[3];   // [256, 256]
    float* out = (float*)d_out;                // [B, 256]

    const int B = in_sizes[0] / 512;

    prep_kernel<<<768, 256>>>(gw, z);

    cudaFuncSetAttribute(softtree_h4_kernel,
                         cudaFuncAttributeMaxDynamicSharedMemorySize, SMEM_BYTES);
    softtree_h4_kernel<<<B / BM, NT, SMEM_BYTES>>>(x, gb, out);
}

// round 11
// speedup vs baseline: 8.4888x; 1.0289x over previous
#include <cuda_runtime.h>
#include <cuda_fp16.h>
#include <cstdint>

#define GATES 255
#define BM    64
#define NT    256

// Fragment-major fp16 weights (rebuilt every call, deterministic).
__device__ __half g_gwH[512 * 256];   // gate GEMM B: tiles of [64k][256n]
__device__ __half g_zH [256 * 256];   // out  GEMM B: tiles of [64k][256n]

// ---- smem layout (bytes). gates(f32) overlaps A+B bufs (disjoint lifetimes:
// gates are written only after ALL phase-1 cp.async groups retired, and the z
// prefetch into B bufs is issued only after the LAST gates read in the tree.)
#define A_OFF      0u                                  // A frag [64m][64k] fp16 (8KB)
#define B_OFF(b)   (8192u + (unsigned)(b) * 32768u)    // B frag [256n][64k] fp16, x2
#define GATES_OFF  0u                                  // gates [64][257] f32 (65792B)
#define LEAF_OFF   73728u                              // leaf  [64][260] fp16 (33280B)
#define GBS_OFF    107008u                             // 256 f32
#define SMEM_BYTES 108032u
#define GGLS 257
#define LLS  260   // halves; row stride 520 B (divisible by 8 -> uint2 loads aligned)

// fragment-major half index for mma.m16n8k16 (k-tiles of 64)
__host__ __device__ __forceinline__ int bidx16(int k, int n) {
    return (k >> 6) * 16384 + ((n >> 3) * 4 + ((k >> 4) & 3)) * 128
         + ((n & 7) * 4 + ((k >> 1) & 3)) * 4 + ((k >> 3) & 1) * 2 + (k & 1);
}

__device__ __forceinline__ uint32_t smem_u32(const void* p) {
    uint32_t a;
    asm("{ .reg .u64 t; cvta.to.shared.u64 t, %1; cvt.u32.u64 %0, t; }" : "=r"(a) : "l"(p));
    return a;
}
#define CP_ASYNC16(dst, src) \
    asm volatile("cp.async.cg.shared.global [%0], [%1], 16;" :: "r"(dst), "l"(src) : "memory")
#define CP_COMMIT() asm volatile("cp.async.commit_group;" ::: "memory")
#define CP_WAIT(n)  asm volatile("cp.async.wait_group %0;" :: "n"(n) : "memory")

__device__ __forceinline__ void mma16(float* c, const uint32_t* a, uint32_t b0, uint32_t b1) {
    asm volatile("mma.sync.aligned.m16n8k16.row.col.f32.f16.f16.f32 "
        "{%0,%1,%2,%3}, {%4,%5,%6,%7}, {%8,%9}, {%0,%1,%2,%3};"
        : "+f"(c[0]), "+f"(c[1]), "+f"(c[2]), "+f"(c[3])
        : "r"(a[0]), "r"(a[1]), "r"(a[2]), "r"(a[3]), "r"(b0), "r"(b1));
}
__device__ __forceinline__ float sigmoidf_fast(float v) {
    return __fdividef(1.0f, 1.0f + __expf(-v));
}

// A-frag STS address (bytes) for float-quad (row, q): covers k = 4q..4q+3
__device__ __forceinline__ uint32_t afrag_addr(int row, int q) {
    int ra = row >> 4, ks = q >> 2;
    int lane = (row & 7) * 4 + ((2 * q) & 3);
    int reg  = ((row >> 3) & 1) + 2 * ((q >> 1) & 1);
    return (uint32_t)((ra * 4 + ks) * 512 + lane * 16 + reg * 4);
}

// ---- merged prep kernel ----
__global__ void prep_kernel(const float* __restrict__ gw, const float* __restrict__ z) {
    int b = blockIdx.x;
    if (b < 512) {
        int idx = b * 256 + threadIdx.x;            // 131072
        int k = idx >> 8, n = idx & 255;
        float v = (n < GATES) ? gw[k * GATES + n] : 0.0f;
        g_gwH[bidx16(k, n)] = __float2half_rn(v);
    } else {
        int idx = (b - 512) * 256 + threadIdx.x;    // 65536
        int n = idx >> 8, k = idx & 255;
        g_zH[bidx16(k, n)] = __float2half_rn(z[n * 256 + k]);
    }
}

// ---- main fused kernel: one CTA = 64 rows, 8 warps (32m x 64n tiles), 2 CTAs/SM ----
extern "C" __global__ void __launch_bounds__(NT, 2)
softtree_h5_kernel(const float* __restrict__ x,
                   const float* __restrict__ gb,
                   float* __restrict__ out)
{
    extern __shared__ char smc[];
    float*  gates = (float*)(smc + GATES_OFF);
    __half* leaf  = (__half*)(smc + LEAF_OFF);
    float*  gbs   = (float*)(smc + GBS_OFF);
    const uint32_t sb = smem_u32(smc);

    const int tid  = threadIdx.x;
    const int lane = tid & 31;
    const int wid  = tid >> 5;       // 0..7
    const int mg   = wid & 1;        // rows mg*32 .. +31
    const int ng   = wid >> 1;       // cols ng*64 .. +63
    const int g    = lane >> 2;
    const int t4   = lane & 3;
    const int rbase = blockIdx.x * BM;

    gbs[tid] = (tid < GATES) ? gb[tid] : 0.0f;

    float acc[2][8][4];
    #pragma unroll
    for (int ra = 0; ra < 2; ra++)
        #pragma unroll
        for (int j = 0; j < 8; j++)
            #pragma unroll
            for (int e = 0; e < 4; e++) acc[ra][j][e] = 0.0f;

    uint32_t xh[8];

    auto issueB = [&](int buf, const __half* srcTile) {
        const char* s = (const char*)srcTile;
        #pragma unroll
        for (int j = 0; j < 8; j++) {
            uint32_t off = (uint32_t)(tid + j * NT) * 16u;
            CP_ASYNC16(sb + B_OFF(buf) + off, s + off);
        }
    };
    auto ldgA = [&](int t) {
        #pragma unroll
        for (int j = 0; j < 4; j++) {
            int f = j * NT + tid;            // 0..1023
            int row = f >> 4, q = f & 15;
            float4 v = *(const float4*)&x[(size_t)(rbase + row) * 512 + t * 64 + q * 4];
            __half2 h0 = __floats2half2_rn(v.x, v.y);
            __half2 h1 = __floats2half2_rn(v.z, v.w);
            xh[2 * j]     = *(uint32_t*)&h0;
            xh[2 * j + 1] = *(uint32_t*)&h1;
        }
    };
    auto stsA = [&]() {
        #pragma unroll
        for (int j = 0; j < 4; j++) {
            int f = j * NT + tid;
            int row = f >> 4, q = f & 15;
            uint32_t a0 = afrag_addr(row, q);
            *(uint32_t*)(smc + A_OFF + a0)      = xh[2 * j];
            *(uint32_t*)(smc + A_OFF + a0 + 16) = xh[2 * j + 1];
        }
    };
    auto compute = [&](int bb) {
        #pragma unroll
        for (int ks = 0; ks < 4; ks++) {
            uint32_t a0[4], a1[4];
            *(uint4*)a0 = *(const uint4*)(smc + A_OFF + (uint32_t)(((mg * 2)     * 4 + ks) * 512 + lane * 16));
            *(uint4*)a1 = *(const uint4*)(smc + A_OFF + (uint32_t)(((mg * 2 + 1) * 4 + ks) * 512 + lane * 16));
            #pragma unroll
            for (int j = 0; j < 8; j++) {
                uint2 bv = *(const uint2*)(smc + B_OFF(bb) + (uint32_t)(((ng * 8 + j) * 4 + ks) * 256 + lane * 8));
                mma16(acc[0][j], a0, bv.x, bv.y);
                mma16(acc[1][j], a1, bv.x, bv.y);
            }
        }
    };

    // ============ Phase 1: logits = x @ gwT (8 K-tiles, B 2-buf, A 1-buf) ============
    issueB(0, g_gwH);           CP_COMMIT();
    issueB(1, g_gwH + 16384);   CP_COMMIT();
    ldgA(0);  stsA();  ldgA(1);

    #pragma unroll 1
    for (int t = 0; t < 8; t++) {
        if (t < 7) { CP_WAIT(1); } else { CP_WAIT(0); }
        __syncthreads();
        compute(t & 1);
        __syncthreads();
        if (t <= 5) { issueB(t & 1, g_gwH + (size_t)(t + 2) * 16384); CP_COMMIT(); }
        if (t < 7) { stsA(); if (t < 6) ldgA(t + 2); }
    }
    // all phase-1 cp.async retired (CP_WAIT(0) at t=7): A/B bufs are dead ->
    // the gates region (overlapping them) is now safe to write.

    // ============ bias + sigmoid -> gates (f32) ============
    #pragma unroll
    for (int ra = 0; ra < 2; ra++)
        #pragma unroll
        for (int j = 0; j < 8; j++) {
            int row = mg * 32 + ra * 16 + g;
            int col = ng * 64 + j * 8 + 2 * t4;
            gates[row * GGLS + col]           = sigmoidf_fast(acc[ra][j][0] + gbs[col]);
            gates[row * GGLS + col + 1]       = sigmoidf_fast(acc[ra][j][1] + gbs[col + 1]);
            gates[(row + 8) * GGLS + col]     = sigmoidf_fast(acc[ra][j][2] + gbs[col]);
            gates[(row + 8) * GGLS + col + 1] = sigmoidf_fast(acc[ra][j][3] + gbs[col + 1]);
        }
    __syncthreads();

    // ============ tree products -> leaf fp16 (each thread: row r, 2 leaf-blocks) ============
    {
        const int r = tid & 63;
        const float* grow = &gates[r * GGLS];
        #pragma unroll
        for (int s = 0; s < 2; s++) {
            const int h8 = (tid >> 6) + 4 * s;   // 0..7, leaves h8*32 .. +31

            float p;
            { float g0 = grow[0];             p = (h8 >> 2) ? 1.0f - g0 : g0; }
            { float g1 = grow[1 + (h8 >> 2)]; p = ((h8 >> 1) & 1) ? p - p * g1 : p * g1; }
            { float g2 = grow[3 + (h8 >> 1)]; p = (h8 & 1) ? p - p * g2 : p * g2; }
            float Q1[2];
            { float gg = grow[7 + h8]; Q1[0] = p * gg; Q1[1] = p - Q1[0]; }
            float Q2[4];
            #pragma unroll
            for (int i = 0; i < 2; i++) {
                float gg = grow[15 + 2 * h8 + i];
                Q2[2 * i] = Q1[i] * gg; Q2[2 * i + 1] = Q1[i] - Q2[2 * i];
            }
            float Q3[8];
            #pragma unroll
            for (int i = 0; i < 4; i++) {
                float gg = grow[31 + 4 * h8 + i];
                Q3[2 * i] = Q2[i] * gg; Q3[2 * i + 1] = Q2[i] - Q3[2 * i];
            }
            __half* lrow = &leaf[r * LLS + h8 * 32];
            #pragma unroll
            for (int i = 0; i < 8; i++) {
                float gg = grow[63 + 8 * h8 + i];
                float qa = Q3[i] * gg, qb = Q3[i] - qa;
                float g5a = grow[127 + 16 * h8 + 2 * i];
                float v0 = qa * g5a, v1 = qa - v0;
                *(__half2*)&lrow[4 * i] = __floats2half2_rn(v0, v1);
                float g5b = grow[127 + 16 * h8 + 2 * i + 1];
                float v2 = qb * g5b, v3 = qb - v2;
                *(__half2*)&lrow[4 * i + 2] = __floats2half2_rn(v2, v3);
            }
        }
    }
    __syncthreads();   // ALL gates reads retired -> B bufs (overlapping gates) reusable

    // ============ Phase 3: out = leaf @ z^T (4 K-tiles) ============
    #pragma unroll
    for (int ra = 0; ra < 2; ra++)
        #pragma unroll
        for (int j = 0; j < 8; j++)
            #pragma unroll
            for (int e = 0; e < 4; e++) acc[ra][j][e] = 0.0f;

    auto fillA = [&](int t) {
        #pragma unroll
        for (int j = 0; j < 4; j++) {
            int f = j * NT + tid;
            int row = f >> 4, q = f & 15;
            uint2 u = *(const uint2*)&leaf[row * LLS + t * 64 + q * 4];
            uint32_t a0 = afrag_addr(row, q);
            *(uint32_t*)(smc + A_OFF + a0)      = u.x;
            *(uint32_t*)(smc + A_OFF + a0 + 16) = u.y;
        }
    };

    issueB(0, g_zH);           CP_COMMIT();
    issueB(1, g_zH + 16384);   CP_COMMIT();
    fillA(0);

    #pragma unroll 1
    for (int t = 0; t < 4; t++) {
        if (t < 3) { CP_WAIT(1); } else { CP_WAIT(0); }
        __syncthreads();
        compute(t & 1);
        __syncthreads();
        if (t <= 1) { issueB(t & 1, g_zH + (size_t)(t + 2) * 16384); CP_COMMIT(); }
        if (t < 3) fillA(t + 1);
    }

    // ============ write out ============
    #pragma unroll
    for (int ra = 0; ra < 2; ra++)
        #pragma unroll
        for (int j = 0; j < 8; j++) {
            int row = rbase + mg * 32 + ra * 16 + g;
            int col = ng * 64 + j * 8 + 2 * t4;
            float2 s0, s1;
            s0.x = acc[ra][j][0]; s0.y = acc[ra][j][1];
            s1.x = acc[ra][j][2]; s1.y = acc[ra][j][3];
            *(float2*)&out[(size_t)row * 256 + col]       = s0;
            *(float2*)&out[(size_t)(row + 8) * 256 + col] = s1;
        }
}

extern "C" void kernel_launch(void* const* d_in, const int* in_sizes, int n_in,
                              void* d_out, int out_size)
{
    const float* x  = (const float*)d_in[0];   // [B, 512]
    const float* gw = (const float*)d_in[1];   // [512, 255]
    const float* gb = (const float*)d_in[2];   // [255]
    const float* z  = (const float*)d_in[3];   // [256, 256]
    float* out = (float*)d_out;                // [B, 256]

    const int B = in_sizes[0] / 512;

    prep_kernel<<<768, 256>>>(gw, z);

    cudaFuncSetAttribute(softtree_h5_kernel,
                         cudaFuncAttributeMaxDynamicSharedMemorySize, SMEM_BYTES);
    softtree_h5_kernel<<<B / BM, NT, SMEM_BYTES>>>(x, gb, out);
}

// round 12
// speedup vs baseline: 8.5707x; 1.0096x over previous
#include <cuda_runtime.h>
#include <cuda_fp16.h>
#include <cstdint>

#define GATES 255
#define BM    64
#define NT    256

// Fragment-major fp16 weights (rebuilt every call, deterministic).
__device__ __half g_gwH[512 * 256];   // gate GEMM B: 8 tiles of [64k][256n] (16384 halves each)
__device__ __half g_zH [256 * 256];   // out  GEMM B: 4 tiles

// ---- smem layout (bytes) ----
// Lifetimes: {A bufs, B bufs} live in GEMM phases; gates(f32) lives in the middle
// phase and overlaps them (written only after ALL phase-1 cp.async retired + sync;
// phase-3 writes into A/B start only after the tree's last gates read + sync).
// gbs lives from start through sigmoid; leaf (written in tree phase, after the
// post-sigmoid sync) overlaps it.
#define A_OFF(b)   ((unsigned)(b) * 8192u)              // A frag [64m][64k] fp16, x2
#define B_OFF(b)   (16384u + (unsigned)(b) * 32768u)    // B frag [256n][64k] fp16, x2 (ends 81920)
#define GATES_OFF  0u                                   // gates [64][257] f32 (65792 B, inside A+B)
#define LEAF_OFF   81920u                               // leaf  [64][260] fp16 (33280 B)
#define GBS_OFF    81920u                               // 256 f32 (overlaps leaf head)
#define SMEM_BYTES 115200u
#define GGLS 257
#define LLS  260   // halves; 520 B row stride (8-byte aligned for uint2)

__device__ __forceinline__ uint32_t smem_u32(const void* p) {
    uint32_t a;
    asm("{ .reg .u64 t; cvta.to.shared.u64 t, %1; cvt.u32.u64 %0, t; }" : "=r"(a) : "l"(p));
    return a;
}
#define CP_ASYNC16(dst, src) \
    asm volatile("cp.async.cg.shared.global [%0], [%1], 16;" :: "r"(dst), "l"(src) : "memory")
#define CP_COMMIT() asm volatile("cp.async.commit_group;" ::: "memory")
#define CP_WAIT(n)  asm volatile("cp.async.wait_group %0;" :: "n"(n) : "memory")

__device__ __forceinline__ void mma16(float* c, const uint32_t* a, uint32_t b0, uint32_t b1) {
    asm volatile("mma.sync.aligned.m16n8k16.row.col.f32.f16.f16.f32 "
        "{%0,%1,%2,%3}, {%4,%5,%6,%7}, {%8,%9}, {%0,%1,%2,%3};"
        : "+f"(c[0]), "+f"(c[1]), "+f"(c[2]), "+f"(c[3])
        : "r"(a[0]), "r"(a[1]), "r"(a[2]), "r"(a[3]), "r"(b0), "r"(b1));
}
__device__ __forceinline__ float sigmoidf_fast(float v) {
    return __fdividef(1.0f, 1.0f + __expf(-v));
}

// A-frag STS address (bytes within an A buffer) for float-quad (row, q)
__device__ __forceinline__ uint32_t afrag_addr(int row, int q) {
    int ra = row >> 4, ks = q >> 2;
    int lane = (row & 7) * 4 + ((2 * q) & 3);
    int reg  = ((row >> 3) & 1) + 2 * ((q >> 1) & 1);
    return (uint32_t)((ra * 4 + ks) * 512 + lane * 16 + reg * 4);
}

// ---- prep kernel: output-centric, 8 fragment-major halves -> one uint4 store ----
// Inverse of bidx16: idx -> (k, n). For 8 consecutive idx (aligned): the low 3 idx
// bits map to k-offsets {0,1,8,9,2,3,10,11}.
__global__ void prep_kernel(const float* __restrict__ gw, const float* __restrict__ z) {
    const int t8 = (blockIdx.x * 256 + threadIdx.x) * 8;   // 96 blocks -> 196608 halves
    __half h[8];
    if (t8 < 131072) {            // gw -> g_gwH
        int tile = t8 >> 14;
        int rem  = t8 & 16383;
        int c    = rem >> 7;                       // 0..127
        int n    = (c >> 2) * 8 + ((t8 >> 4) & 7);
        int kfix = tile * 64 + (c & 3) * 16 + ((t8 >> 3) & 1) * 4;
        const int koff[8] = {0, 1, 8, 9, 2, 3, 10, 11};
        #pragma unroll
        for (int i = 0; i < 8; i++) {
            int k = kfix + koff[i];
            h[i] = (n < GATES) ? __float2half_rn(gw[k * GATES + n]) : __half(0.0f);
        }
        *(uint4*)&g_gwH[t8] = *(const uint4*)h;
    } else {                      // z -> g_zH
        int t8z  = t8 - 131072;
        int tile = t8z >> 14;
        int rem  = t8z & 16383;
        int c    = rem >> 7;
        int n    = (c >> 2) * 8 + ((t8z >> 4) & 7);
        int kfix = tile * 64 + (c & 3) * 16 + ((t8z >> 3) & 1) * 4;
        const int koff[8] = {0, 1, 8, 9, 2, 3, 10, 11};
        #pragma unroll
        for (int i = 0; i < 8; i++) {
            int k = kfix + koff[i];
            h[i] = __float2half_rn(z[n * 256 + k]);
        }
        *(uint4*)&g_zH[t8z] = *(const uint4*)h;
    }
}

// ---- main fused kernel: one CTA = 64 rows, 8 warps (32m x 64n), 2 CTAs/SM ----
extern "C" __global__ void __launch_bounds__(NT, 2)
softtree_h6_kernel(const float* __restrict__ x,
                   const float* __restrict__ gb,
                   float* __restrict__ out)
{
    extern __shared__ char smc[];
    float*  gates = (float*)(smc + GATES_OFF);
    __half* leaf  = (__half*)(smc + LEAF_OFF);
    float*  gbs   = (float*)(smc + GBS_OFF);
    const uint32_t sb = smem_u32(smc);

    const int tid  = threadIdx.x;
    const int lane = tid & 31;
    const int wid  = tid >> 5;       // 0..7
    const int mg   = wid & 1;        // rows mg*32 .. +31
    const int ng   = wid >> 1;       // cols ng*64 .. +63
    const int g    = lane >> 2;
    const int t4   = lane & 3;
    const int rbase = blockIdx.x * BM;

    gbs[tid] = (tid < GATES) ? gb[tid] : 0.0f;

    float acc[2][8][4];
    #pragma unroll
    for (int ra = 0; ra < 2; ra++)
        #pragma unroll
        for (int j = 0; j < 8; j++)
            #pragma unroll
            for (int e = 0; e < 4; e++) acc[ra][j][e] = 0.0f;

    uint32_t xh[8];

    auto issueB = [&](int buf, const __half* srcTile) {
        const char* s = (const char*)srcTile;
        #pragma unroll
        for (int j = 0; j < 8; j++) {
            uint32_t off = (uint32_t)(tid + j * NT) * 16u;
            CP_ASYNC16(sb + B_OFF(buf) + off, s + off);
        }
    };
    auto ldgA = [&](int t) {
        #pragma unroll
        for (int j = 0; j < 4; j++) {
            int f = j * NT + tid;            // 0..1023
            int row = f >> 4, q = f & 15;
            float4 v = *(const float4*)&x[(size_t)(rbase + row) * 512 + t * 64 + q * 4];
            __half2 h0 = __floats2half2_rn(v.x, v.y);
            __half2 h1 = __floats2half2_rn(v.z, v.w);
            xh[2 * j]     = *(uint32_t*)&h0;
            xh[2 * j + 1] = *(uint32_t*)&h1;
        }
    };
    auto stsA = [&](int buf) {
        #pragma unroll
        for (int j = 0; j < 4; j++) {
            int f = j * NT + tid;
            int row = f >> 4, q = f & 15;
            uint32_t a0 = afrag_addr(row, q);
            *(uint32_t*)(smc + A_OFF(buf) + a0)      = xh[2 * j];
            *(uint32_t*)(smc + A_OFF(buf) + a0 + 16) = xh[2 * j + 1];
        }
    };
    auto compute = [&](int ab, int bb) {
        #pragma unroll
        for (int ks = 0; ks < 4; ks++) {
            uint32_t a0[4], a1[4];
            *(uint4*)a0 = *(const uint4*)(smc + A_OFF(ab) + (uint32_t)(((mg * 2)     * 4 + ks) * 512 + lane * 16));
            *(uint4*)a1 = *(const uint4*)(smc + A_OFF(ab) + (uint32_t)(((mg * 2 + 1) * 4 + ks) * 512 + lane * 16));
            #pragma unroll
            for (int j = 0; j < 8; j++) {
                uint2 bv = *(const uint2*)(smc + B_OFF(bb) + (uint32_t)(((ng * 8 + j) * 4 + ks) * 256 + lane * 8));
                mma16(acc[0][j], a0, bv.x, bv.y);
                mma16(acc[1][j], a1, bv.x, bv.y);
            }
        }
    };

    // ============ Phase 1: logits = x @ gwT (8 K-tiles, ONE sync per tile) ============
    // Schedule at iter u (post-sync): write A/B buffers for tile u+1 (their last
    // readers ran at iter u-1, covered by this sync), then compute tile u.
    issueB(0, g_gwH);  CP_COMMIT();
    ldgA(0);  stsA(0);  ldgA(1);

    #pragma unroll 1
    for (int u = 0; u < 8; u++) {
        CP_WAIT(0);
        __syncthreads();
        if (u < 7) {
            stsA((u + 1) & 1);                                    // tile u+1 from xh regs
            issueB((u + 1) & 1, g_gwH + (size_t)(u + 1) * 16384); // ready by iter u+1
            CP_COMMIT();
        }
        compute(u & 1, u & 1);
        if (u < 6) ldgA(u + 2);
    }
    __syncthreads();   // compute(7) retired everywhere; A/B dead -> gates writable

    // ============ bias + sigmoid -> gates (f32) ============
    #pragma unroll
    for (int ra = 0; ra < 2; ra++)
        #pragma unroll
        for (int j = 0; j < 8; j++) {
            int row = mg * 32 + ra * 16 + g;
            int col = ng * 64 + j * 8 + 2 * t4;
            gates[row * GGLS + col]           = sigmoidf_fast(acc[ra][j][0] + gbs[col]);
            gates[row * GGLS + col + 1]       = sigmoidf_fast(acc[ra][j][1] + gbs[col + 1]);
            gates[(row + 8) * GGLS + col]     = sigmoidf_fast(acc[ra][j][2] + gbs[col]);
            gates[(row + 8) * GGLS + col + 1] = sigmoidf_fast(acc[ra][j][3] + gbs[col + 1]);
        }
    __syncthreads();   // gates visible; gbs reads done -> leaf (overlapping gbs) writable

    // ============ tree products -> leaf fp16 ============
    {
        const int r = tid & 63;
        const float* grow = &gates[r * GGLS];
        #pragma unroll
        for (int s = 0; s < 2; s++) {
            const int h8 = (tid >> 6) + 4 * s;   // 0..7, leaves h8*32 .. +31

            float p;
            { float g0 = grow[0];             p = (h8 >> 2) ? 1.0f - g0 : g0; }
            { float g1 = grow[1 + (h8 >> 2)]; p = ((h8 >> 1) & 1) ? p - p * g1 : p * g1; }
            { float g2 = grow[3 + (h8 >> 1)]; p = (h8 & 1) ? p - p * g2 : p * g2; }
            float Q1[2];
            { float gg = grow[7 + h8]; Q1[0] = p * gg; Q1[1] = p - Q1[0]; }
            float Q2[4];
            #pragma unroll
            for (int i = 0; i < 2; i++) {
                float gg = grow[15 + 2 * h8 + i];
                Q2[2 * i] = Q1[i] * gg; Q2[2 * i + 1] = Q1[i] - Q2[2 * i];
            }
            float Q3[8];
            #pragma unroll
            for (int i = 0; i < 4; i++) {
                float gg = grow[31 + 4 * h8 + i];
                Q3[2 * i] = Q2[i] * gg; Q3[2 * i + 1] = Q2[i] - Q3[2 * i];
            }
            __half* lrow = &leaf[r * LLS + h8 * 32];
            #pragma unroll
            for (int i = 0; i < 8; i++) {
                float gg = grow[63 + 8 * h8 + i];
                float qa = Q3[i] * gg, qb = Q3[i] - qa;
                float g5a = grow[127 + 16 * h8 + 2 * i];
                float v0 = qa * g5a, v1 = qa - v0;
                *(__half2*)&lrow[4 * i] = __floats2half2_rn(v0, v1);
                float g5b = grow[127 + 16 * h8 + 2 * i + 1];
                float v2 = qb * g5b, v3 = qb - v2;
                *(__half2*)&lrow[4 * i + 2] = __floats2half2_rn(v2, v3);
            }
        }
    }
    __syncthreads();   // ALL gates reads retired -> A/B bufs (overlapping gates) reusable

    // ============ Phase 3: out = leaf @ z^T (4 K-tiles, ONE sync per tile) ============
    #pragma unroll
    for (int ra = 0; ra < 2; ra++)
        #pragma unroll
        for (int j = 0; j < 8; j++)
            #pragma unroll
            for (int e = 0; e < 4; e++) acc[ra][j][e] = 0.0f;

    auto fillA = [&](int t, int buf) {
        #pragma unroll
        for (int j = 0; j < 4; j++) {
            int f = j * NT + tid;
            int row = f >> 4, q = f & 15;
            uint2 u2 = *(const uint2*)&leaf[row * LLS + t * 64 + q * 4];
            uint32_t a0 = afrag_addr(row, q);
            *(uint32_t*)(smc + A_OFF(buf) + a0)      = u2.x;
            *(uint32_t*)(smc + A_OFF(buf) + a0 + 16) = u2.y;
        }
    };

    issueB(0, g_zH);  CP_COMMIT();
    fillA(0, 0);

    #pragma unroll 1
    for (int u = 0; u < 4; u++) {
        CP_WAIT(0);
        __syncthreads();
        if (u < 3) {
            fillA(u + 1, (u + 1) & 1);
            issueB((u + 1) & 1, g_zH + (size_t)(u + 1) * 16384);
            CP_COMMIT();
        }
        compute(u & 1, u & 1);
    }

    // ============ write out ============
    #pragma unroll
    for (int ra = 0; ra < 2; ra++)
        #pragma unroll
        for (int j = 0; j < 8; j++) {
            int row = rbase + mg * 32 + ra * 16 + g;
            int col = ng * 64 + j * 8 + 2 * t4;
            float2 s0, s1;
            s0.x = acc[ra][j][0]; s0.y = acc[ra][j][1];
            s1.x = acc[ra][j][2]; s1.y = acc[ra][j][3];
            *(float2*)&out[(size_t)row * 256 + col]       = s0;
            *(float2*)&out[(size_t)(row + 8) * 256 + col] = s1;
        }
}

extern "C" void kernel_launch(void* const* d_in, const int* in_sizes, int n_in,
                              void* d_out, int out_size)
{
    const float* x  = (const float*)d_in[0];   // [B, 512]
    const float* gw = (const float*)d_in[1];   // [512, 255]
    const float* gb = (const float*)d_in[2];   // [255]
    const float* z  = (const float*)d_in[3];   // [256, 256]
    float* out = (float*)d_out;                // [B, 256]

    const int B = in_sizes[0] / 512;

    prep_kernel<<<96, 256>>>(gw, z);

    cudaFuncSetAttribute(softtree_h6_kernel,
                         cudaFuncAttributeMaxDynamicSharedMemorySize, SMEM_BYTES);
    softtree_h6_kernel<<<B / BM, NT, SMEM_BYTES>>>(x, gb, out);
}